// round 14
// baseline (speedup 1.0000x reference)
#include <cuda_runtime.h>
#include <cuda_bf16.h>
#include <cstdint>

#define NPAD 20032
#define MAXB 2048
#define MAXN 20000
#define MAXL 100
#define NS1  9
#define NS2  4
#define RS   72   // smem row stride in floats; RS%32==8 -> conflict-free float2 frags

// ---------------- static device scratch (tf32-rounded; contraction dims k-permuted) ----------------
__device__ __align__(16) float g_x32[MAXB * 64];
__device__ __align__(16) float g_sf32[NPAD * 64];
__device__ __align__(16) float g_f132[NPAD * 64];
__device__ __align__(16) float g_f232[NPAD * 64];
__device__ __align__(16) float g_V32[(size_t)128 * NPAD];   // [c][i-perm]
__device__ __align__(16) float g_slT32[(size_t)32 * NPAD];  // [c][i-perm]
__device__ __align__(16) float g_xt321[MAXB * 64];
__device__ __align__(16) float g_xt322[MAXB * 64];
__device__ __align__(16) __nv_bfloat16 g_ldtb[2 * MAXL * MAXL];
__device__ __align__(16) float g_xnorm[MAXB];
__device__ __align__(16) float g_snorm[NPAD];    // padded with 1e4
__device__ __align__(16) float g_f1norm[NPAD];
__device__ __align__(16) float g_f2norm[NPAD];
__device__ __align__(16) int   g_li1p[NPAD];
__device__ __align__(16) int   g_li2p[NPAD];
__device__ int   g_match[MAXB];
__device__ float g_acc1[MAXB * 64];
__device__ float g_acc2[MAXB * 64];
__device__ float g_den[MAXB];
__device__ float g_xtn1[MAXB];
__device__ float g_xtn2[MAXB];
__device__ int   g_yidx1[MAXB];
__device__ int   g_yidx2[MAXB];
__device__ float g_out2[2 * MAXB * 32];
__device__ float g_den2[2 * MAXB];

// ---------------- helpers ----------------
__device__ __forceinline__ uint32_t saddr(const void* p) {
    return (uint32_t)__cvta_generic_to_shared(p);
}
__device__ __forceinline__ void cpa16(uint32_t dst, const void* src) {
    asm volatile("cp.async.cg.shared.global [%0], [%1], 16;" :: "r"(dst), "l"(src));
}
__device__ __forceinline__ void cpa_commit() {
    asm volatile("cp.async.commit_group;" ::: "memory");
}
__device__ __forceinline__ void cpa_wait0() {
    asm volatile("cp.async.wait_group 0;" ::: "memory");
}
__device__ __forceinline__ float tf32r(float f) {
    uint32_t u; asm("cvt.rna.tf32.f32 %0, %1;" : "=r"(u) : "f"(f));
    return __uint_as_float(u);
}
__device__ __forceinline__ void mma_tf32(float* c, uint32_t a0, uint32_t a1, uint32_t a2, uint32_t a3,
                                         uint32_t b0, uint32_t b1) {
    asm volatile("mma.sync.aligned.m16n8k8.row.col.f32.tf32.tf32.f32 "
                 "{%0,%1,%2,%3}, {%4,%5,%6,%7}, {%8,%9}, {%0,%1,%2,%3};"
                 : "+f"(c[0]), "+f"(c[1]), "+f"(c[2]), "+f"(c[3])
                 : "r"(a0), "r"(a1), "r"(a2), "r"(a3), "r"(b0), "r"(b1));
}
// permuted position of logical index k within its 8-group: order 0,4,1,5,2,6,3,7
__device__ __forceinline__ int kperm(int k) {
    return (k & ~7) | (((k & 3) << 1) | ((k >> 2) & 1));
}

// ---------------- prep kernels ----------------
__global__ void init_kernel(int B) {
    int i = blockIdx.x * 256 + threadIdx.x;
    if (i < B * 64) { g_acc1[i] = 0.f; g_acc2[i] = 0.f; }
    if (i < 2 * B * 32) g_out2[i] = 0.f;
    if (i < B) {
        g_den[i] = 0.f; g_match[i] = 0x7fffffff;
        g_den2[i] = 0.f; g_den2[B + i] = 0.f;
    }
}

__global__ void cvt32_kernel(const float* __restrict__ x, const float* __restrict__ sf,
                             const float* __restrict__ f1, const float* __restrict__ f2,
                             int B, int N) {
    int r = blockIdx.x * blockDim.x + threadIdx.x;
    const float* src; float* dst; float* ndst; int row, nrow;
    if (r < NPAD)          { src = sf; dst = g_sf32; ndst = g_snorm;  row = r;            nrow = N; }
    else if (r < 2 * NPAD) { src = f1; dst = g_f132; ndst = g_f1norm; row = r - NPAD;     nrow = N; }
    else if (r < 3 * NPAD) { src = f2; dst = g_f232; ndst = g_f2norm; row = r - 2 * NPAD; nrow = N; }
    else                   { src = x;  dst = g_x32;  ndst = g_xnorm;  row = r - 3 * NPAD; nrow = B;
                             if (row >= B) return; }
    bool ok = row < nrow;
    float s = 0.f;
#pragma unroll
    for (int kk = 0; kk < 8; kk++) {
        float4 v0 = ok ? ((const float4*)(src + (size_t)row * 64))[2 * kk]     : make_float4(0.f, 0.f, 0.f, 0.f);
        float4 v1 = ok ? ((const float4*)(src + (size_t)row * 64))[2 * kk + 1] : make_float4(0.f, 0.f, 0.f, 0.f);
        float a0 = tf32r(v0.x), a1 = tf32r(v0.y), a2 = tf32r(v0.z), a3 = tf32r(v0.w);
        float a4 = tf32r(v1.x), a5 = tf32r(v1.y), a6 = tf32r(v1.z), a7 = tf32r(v1.w);
        ((float4*)(dst + (size_t)row * 64))[2 * kk]     = make_float4(a0, a4, a1, a5);
        ((float4*)(dst + (size_t)row * 64))[2 * kk + 1] = make_float4(a2, a6, a3, a7);
        s = fmaf(a0, a0, fmaf(a1, a1, fmaf(a2, a2, fmaf(a3, a3, s))));
        s = fmaf(a4, a4, fmaf(a5, a5, fmaf(a6, a6, fmaf(a7, a7, s))));
    }
    ndst[row] = ok ? s : 1e4f;
}

__global__ void cvtT32_kernel(const float* __restrict__ f1, const float* __restrict__ f2,
                              const float* __restrict__ sl, int N) {
    __shared__ float tile[32][33];
    int combo = blockIdx.y;
    int i0 = blockIdx.x * 32;
    const float* src; float* dst; int d0, ncol, outrow0;
    if (combo < 2)      { src = f1; dst = g_V32;   d0 = combo * 32;       ncol = 64; outrow0 = d0; }
    else if (combo < 4) { src = f2; dst = g_V32;   d0 = (combo - 2) * 32; ncol = 64; outrow0 = 64 + d0; }
    else                { src = sl; dst = g_slT32; d0 = 0;                ncol = 32; outrow0 = 0; }
    int txx = threadIdx.x, tyy = threadIdx.y;
#pragma unroll
    for (int r = tyy; r < 32; r += 8) {
        int i = i0 + r;
        tile[r][txx] = (i < N) ? src[(size_t)i * ncol + d0 + txx] : 0.f;
    }
    __syncthreads();
#pragma unroll
    for (int rr = tyy; rr < 32; rr += 8)
        dst[(size_t)(outrow0 + rr) * NPAD + i0 + kperm(txx)] = tf32r(tile[txx][rr]);
}

__global__ void cvtldt_kernel(const float* __restrict__ ld1, const float* __restrict__ ld2,
                              const int* __restrict__ li1, const int* __restrict__ li2,
                              int N, int L) {
    int i = blockIdx.x * 256 + threadIdx.x;
    if (i < L * L) {
        g_ldtb[i] = __float2bfloat16(0.01f * ld1[i]);
        g_ldtb[MAXL * MAXL + i] = __float2bfloat16(0.01f * ld2[i]);
    }
    if (i < NPAD) {
        g_li1p[i] = (i < N) ? li1[i] * L : 0;
        g_li2p[i] = (i < N) ? li2[i] * L : 0;
    }
}

// ---------------- Pass 1 (tf32 HMMA, 512 threads, split-j/split-c warp pairs) ----------------
struct __align__(16) SmP1 {
    float Qs[128][RS];
    float Es[128][RS];
    float Ks[2][64][RS];
    float VTs[2][128][RS];
    float knp[2][64];
};

__global__ void __launch_bounds__(512, 1) pass1_kernel(int B, int N, int chunk) {
    extern __shared__ char smraw[];
    SmP1& sm = *reinterpret_cast<SmP1*>(smraw);
    int t = threadIdx.x, w = t >> 5, lane = t & 31, g = lane >> 2, tt = lane & 3;
    int wq = w & 7, wh = w >> 3;                 // q-group / half index
    int qbase = blockIdx.x * 128;
    int i0base = blockIdx.y * chunk;
    int iend = min(i0base + chunk, NPAD);
    int ntl = (iend - i0base) >> 6;
    int qA = wq * 16 + g, qB = qA + 8;
    float qnA = g_xnorm[qbase + qA], qnB = g_xnorm[qbase + qB];

#pragma unroll
    for (int k = 0; k < 4; k++) {
        int gc = t + 512 * k, row = gc >> 4, ch = gc & 15;
        cpa16(saddr(&sm.Qs[row][ch * 4]), g_x32 + (size_t)(qbase + row) * 64 + ch * 4);
    }
#define P1_LOAD(i0v, bi)                                                                   \
    {                                                                                      \
        _Pragma("unroll") for (int k = 0; k < 2; k++) {                                    \
            int gc = t + 512 * k, row = gc >> 4, ch = gc & 15;                             \
            cpa16(saddr(&sm.Ks[bi][row][ch * 4]), g_sf32 + (size_t)((i0v) + row) * 64 + ch * 4); } \
        _Pragma("unroll") for (int k = 0; k < 4; k++) {                                    \
            int gc = t + 512 * k, row = gc >> 4, ch = gc & 15;                             \
            cpa16(saddr(&sm.VTs[bi][row][ch * 4]), g_V32 + (size_t)row * NPAD + (i0v) + ch * 4); } \
        if (t < 16) cpa16(saddr(&sm.knp[bi][t * 4]), g_snorm + (i0v) + t * 4);             \
        cpa_commit();                                                                      \
    }
    P1_LOAD(i0base, 0);

    float C2[8][4];
#pragma unroll
    for (int a = 0; a < 8; a++) { C2[a][0] = 0.f; C2[a][1] = 0.f; C2[a][2] = 0.f; C2[a][3] = 0.f; }
    float denA = 0.f, denB = 0.f;
    int mmA = 0x7fffffff, mmB = 0x7fffffff;

    for (int it = 0; it < ntl; it++) {
        int bi = it & 1;
        int i0 = i0base + it * 64;
        cpa_wait0();
        __syncthreads();
        if (it + 1 < ntl) P1_LOAD(i0 + 64, bi ^ 1);

        // ---- QK: this warp covers j in [wh*32, wh*32+32) ----
        float c[4][4];
#pragma unroll
        for (int a = 0; a < 4; a++) { c[a][0] = 0.f; c[a][1] = 0.f; c[a][2] = 0.f; c[a][3] = 0.f; }
#pragma unroll
        for (int kt = 0; kt < 8; kt++) {
            float2 aA = *(const float2*)&sm.Qs[qA][kt * 8 + 2 * tt];
            float2 aB = *(const float2*)&sm.Qs[qB][kt * 8 + 2 * tt];
            uint32_t a0 = __float_as_uint(aA.x), a1 = __float_as_uint(aB.x);
            uint32_t a2 = __float_as_uint(aA.y), a3 = __float_as_uint(aB.y);
#pragma unroll
            for (int nt = 0; nt < 4; nt++) {
                float2 b = *(const float2*)&sm.Ks[bi][(wh * 4 + nt) * 8 + g][kt * 8 + 2 * tt];
                mma_tf32(c[nt], a0, a1, a2, a3, __float_as_uint(b.x), __float_as_uint(b.y));
            }
        }

        // ---- scores -> E (this warp's j-half) ----
#pragma unroll
        for (int nt = 0; nt < 4; nt++) {
            int j0 = (wh * 4 + nt) * 8 + 2 * tt;
            float k0 = sm.knp[bi][j0], k1 = sm.knp[bi][j0 + 1];
            float rA0 = qnA + k0 - 2.f * c[nt][0];
            float rA1 = qnA + k1 - 2.f * c[nt][1];
            float rB0 = qnB + k0 - 2.f * c[nt][2];
            float rB1 = qnB + k1 - 2.f * c[nt][3];
            if (rA0 <= 2e-4f) mmA = min(mmA, i0 + j0);
            if (rA1 <= 2e-4f) mmA = min(mmA, i0 + j0 + 1);
            if (rB0 <= 2e-4f) mmB = min(mmB, i0 + j0);
            if (rB1 <= 2e-4f) mmB = min(mmB, i0 + j0 + 1);
            float eA0 = tf32r(__expf(-fmaxf(rA0, 0.f)));
            float eA1 = tf32r(__expf(-fmaxf(rA1, 0.f)));
            float eB0 = tf32r(__expf(-fmaxf(rB0, 0.f)));
            float eB1 = tf32r(__expf(-fmaxf(rB1, 0.f)));
            denA += eA0 + eA1; denB += eB0 + eB1;
            *(float2*)&sm.Es[qA][j0] = make_float2(eA0, eA1);
            *(float2*)&sm.Es[qB][j0] = make_float2(eB0, eB1);
        }
        __syncthreads();   // E rows assembled by warp pairs

        // ---- EV: this warp covers V cols [wh*64, wh*64+64), all 64 j ----
#pragma unroll
        for (int ekt = 0; ekt < 8; ekt++) {
            uint32_t a0 = *(const uint32_t*)&sm.Es[qA][ekt * 8 + tt];
            uint32_t a1 = *(const uint32_t*)&sm.Es[qB][ekt * 8 + tt];
            uint32_t a2 = *(const uint32_t*)&sm.Es[qA][ekt * 8 + tt + 4];
            uint32_t a3 = *(const uint32_t*)&sm.Es[qB][ekt * 8 + tt + 4];
#pragma unroll
            for (int nt2 = 0; nt2 < 8; nt2++) {
                float2 b = *(const float2*)&sm.VTs[bi][(wh * 8 + nt2) * 8 + g][ekt * 8 + 2 * tt];
                mma_tf32(C2[nt2], a0, a1, a2, a3, __float_as_uint(b.x), __float_as_uint(b.y));
            }
        }
    }

    // ---- epilogue: this warp owns cols [wh*64 .. wh*64+64) -> acc1 (wh=0) / acc2 (wh=1) ----
    float* base = wh ? g_acc2 : g_acc1;
#pragma unroll
    for (int nt2 = 0; nt2 < 8; nt2++) {
        int cc = nt2 * 8 + 2 * tt;
        atomicAdd(base + (size_t)(qbase + qA) * 64 + cc,     C2[nt2][0]);
        atomicAdd(base + (size_t)(qbase + qA) * 64 + cc + 1, C2[nt2][1]);
        atomicAdd(base + (size_t)(qbase + qB) * 64 + cc,     C2[nt2][2]);
        atomicAdd(base + (size_t)(qbase + qB) * 64 + cc + 1, C2[nt2][3]);
    }
    denA += __shfl_xor_sync(0xffffffffu, denA, 1);
    denA += __shfl_xor_sync(0xffffffffu, denA, 2);
    denB += __shfl_xor_sync(0xffffffffu, denB, 1);
    denB += __shfl_xor_sync(0xffffffffu, denB, 2);
    mmA = min(mmA, __shfl_xor_sync(0xffffffffu, mmA, 1));
    mmA = min(mmA, __shfl_xor_sync(0xffffffffu, mmA, 2));
    mmB = min(mmB, __shfl_xor_sync(0xffffffffu, mmB, 1));
    mmB = min(mmB, __shfl_xor_sync(0xffffffffu, mmB, 2));
    if (tt == 0) {
        atomicAdd(&g_den[qbase + qA], denA);
        atomicAdd(&g_den[qbase + qB], denB);
        if (mmA != 0x7fffffff) atomicMin(&g_match[qbase + qA], mmA);
        if (mmB != 0x7fffffff) atomicMin(&g_match[qbase + qB], mmB);
    }
}

// ---------------- mid ----------------
__global__ void mid_kernel(const float* __restrict__ f1, const float* __restrict__ f2,
                           const float* __restrict__ W1, const float* __restrict__ b1,
                           const float* __restrict__ W2, const float* __restrict__ b2,
                           const float* __restrict__ u1, const float* __restrict__ u2,
                           int B, int N, int DY, int L) {
    __shared__ float sxt[8][2][64];
    __shared__ float sy[8][2][32];
    int wl = threadIdx.x >> 5;
    int lane = threadIdx.x & 31;
    int b = blockIdx.x * 8 + wl;
    if (b >= B) return;

    float inv = 1.0f / g_den[b];
    int d0 = lane, d1 = lane + 32;
    float x10 = g_acc1[(size_t)b * 64 + d0] * inv;
    float x11 = g_acc1[(size_t)b * 64 + d1] * inv;
    float x20 = g_acc2[(size_t)b * 64 + d0] * inv;
    float x21 = g_acc2[(size_t)b * 64 + d1] * inv;
    int m = g_match[b];
    if (m < N) {
        x10 = f1[(size_t)m * 64 + d0]; x11 = f1[(size_t)m * 64 + d1];
        x20 = f2[(size_t)m * 64 + d0]; x21 = f2[(size_t)m * 64 + d1];
    }
    float r10 = tf32r(x10), r11 = tf32r(x11), r20 = tf32r(x20), r21 = tf32r(x21);
    int p0 = kperm(d0), p1 = kperm(d1);
    g_xt321[b * 64 + p0] = r10; g_xt321[b * 64 + p1] = r11;
    g_xt322[b * 64 + p0] = r20; g_xt322[b * 64 + p1] = r21;
    sxt[wl][0][d0] = x10; sxt[wl][0][d1] = x11;
    sxt[wl][1][d0] = x20; sxt[wl][1][d1] = x21;
    float nr1 = r10 * r10 + r11 * r11;
    float nr2 = r20 * r20 + r21 * r21;
#pragma unroll
    for (int o = 16; o; o >>= 1) {
        nr1 += __shfl_xor_sync(0xffffffffu, nr1, o);
        nr2 += __shfl_xor_sync(0xffffffffu, nr2, o);
    }
    if (lane == 0) { g_xtn1[b] = nr1; g_xtn2[b] = nr2; }
    __syncwarp();

    if (lane < DY) {
        float y1 = b1[lane], y2 = b2[lane];
#pragma unroll
        for (int d = 0; d < 64; d++) {
            y1 = fmaf(sxt[wl][0][d], W1[d * DY + lane], y1);
            y2 = fmaf(sxt[wl][1][d], W2[d * DY + lane], y2);
        }
        sy[wl][0][lane] = y1; sy[wl][1][lane] = y2;
    }
    __syncwarp();

    float best1 = 1e38f, best2 = 1e38f; int bi1 = 0x7fffffff, bi2 = 0x7fffffff;
    for (int lab = lane; lab < L; lab += 32) {
        float s1 = 0.f, s2 = 0.f;
        for (int dy = 0; dy < DY; dy++) {
            float t1 = sy[wl][0][dy] - u1[lab * DY + dy]; s1 = fmaf(t1, t1, s1);
            float t2 = sy[wl][1][dy] - u2[lab * DY + dy]; s2 = fmaf(t2, t2, s2);
        }
        if (s1 < best1) { best1 = s1; bi1 = lab; }
        if (s2 < best2) { best2 = s2; bi2 = lab; }
    }
#pragma unroll
    for (int o = 16; o; o >>= 1) {
        float ob = __shfl_xor_sync(0xffffffffu, best1, o);
        int obi  = __shfl_xor_sync(0xffffffffu, bi1, o);
        if (ob < best1 || (ob == best1 && obi < bi1)) { best1 = ob; bi1 = obi; }
        ob  = __shfl_xor_sync(0xffffffffu, best2, o);
        obi = __shfl_xor_sync(0xffffffffu, bi2, o);
        if (ob < best2 || (ob == best2 && obi < bi2)) { best2 = ob; bi2 = obi; }
    }
    if (lane == 0) { g_yidx1[b] = bi1; g_yidx2[b] = bi2; }
}

// ---------------- Pass 2 (tf32 HMMA, 512 threads, split warp pairs) ----------------
struct __align__(16) SmP2 {
    float Qs[128][RS];
    float Es[128][RS];
    float Ks[2][64][RS];
    float VTs[2][32][RS];
    float knp[2][64];
    int   jli[2][64];
    __nv_bfloat16 ldp[MAXL * MAXL];
};

__global__ void __launch_bounds__(512, 1) pass2_kernel(int B, int N, int L, int chunk) {
    extern __shared__ char smraw[];
    SmP2& sm = *reinterpret_cast<SmP2*>(smraw);
    int t = threadIdx.x, w = t >> 5, lane = t & 31, g = lane >> 2, tt = lane & 3;
    int wq = w & 7, wh = w >> 3;
    int z = blockIdx.z;
    const float* Qg = z ? g_xt322 : g_xt321;
    const float* Kg = z ? g_f232 : g_f132;
    const float* kng = z ? g_f2norm : g_f1norm;
    const float* qng = z ? g_xtn2 : g_xtn1;
    const int* lip = z ? g_li2p : g_li1p;
    const int* yix = z ? g_yidx2 : g_yidx1;

    int qbase = blockIdx.x * 128;
    int i0base = blockIdx.y * chunk;
    int iend = min(i0base + chunk, NPAD);
    int ntl = (iend - i0base) >> 6;
    int qA = wq * 16 + g, qB = qA + 8;
    float qnA = qng[qbase + qA], qnB = qng[qbase + qB];
    int yvA = yix[qbase + qA], yvB = yix[qbase + qB];

#pragma unroll
    for (int k = 0; k < 4; k++) {
        int gc = t + 512 * k, row = gc >> 4, ch = gc & 15;
        cpa16(saddr(&sm.Qs[row][ch * 4]), Qg + (size_t)(qbase + row) * 64 + ch * 4);
    }
#pragma unroll
    for (int k = 0; k < 3; k++) {
        int gc = t + 512 * k;
        if (gc < 1250)
            cpa16(saddr((char*)sm.ldp + gc * 16),
                  (const char*)(g_ldtb + (size_t)z * MAXL * MAXL) + gc * 16);
    }
#define P2_LOAD(i0v, bi)                                                                   \
    {                                                                                      \
        _Pragma("unroll") for (int k = 0; k < 2; k++) {                                    \
            int gc = t + 512 * k, row = gc >> 4, ch = gc & 15;                             \
            cpa16(saddr(&sm.Ks[bi][row][ch * 4]), Kg + (size_t)((i0v) + row) * 64 + ch * 4); } \
        {                                                                                  \
            int row = t >> 4, ch = t & 15;                                                 \
            if (row < 32)                                                                  \
                cpa16(saddr(&sm.VTs[bi][row][ch * 4]), g_slT32 + (size_t)row * NPAD + (i0v) + ch * 4); } \
        if (t < 16) cpa16(saddr(&sm.knp[bi][t * 4]), kng + (i0v) + t * 4);                 \
        else if (t < 32) cpa16(saddr(&sm.jli[bi][(t - 16) * 4]), lip + (i0v) + (t - 16) * 4); \
        cpa_commit();                                                                      \
    }
    P2_LOAD(i0base, 0);

    float C2[2][4];
#pragma unroll
    for (int a = 0; a < 2; a++) { C2[a][0] = 0.f; C2[a][1] = 0.f; C2[a][2] = 0.f; C2[a][3] = 0.f; }
    float denA = 0.f, denB = 0.f;

    for (int it = 0; it < ntl; it++) {
        int bi = it & 1;
        cpa_wait0();
        __syncthreads();
        if (it + 1 < ntl) P2_LOAD(i0base + (it + 1) * 64, bi ^ 1);

        // ---- QK (j-half per warp) ----
        float c[4][4];
#pragma unroll
        for (int a = 0; a < 4; a++) { c[a][0] = 0.f; c[a][1] = 0.f; c[a][2] = 0.f; c[a][3] = 0.f; }
#pragma unroll
        for (int kt = 0; kt < 8; kt++) {
            float2 aA = *(const float2*)&sm.Qs[qA][kt * 8 + 2 * tt];
            float2 aB = *(const float2*)&sm.Qs[qB][kt * 8 + 2 * tt];
            uint32_t a0 = __float_as_uint(aA.x), a1 = __float_as_uint(aB.x);
            uint32_t a2 = __float_as_uint(aA.y), a3 = __float_as_uint(aB.y);
#pragma unroll
            for (int nt = 0; nt < 4; nt++) {
                float2 b = *(const float2*)&sm.Ks[bi][(wh * 4 + nt) * 8 + g][kt * 8 + 2 * tt];
                mma_tf32(c[nt], a0, a1, a2, a3, __float_as_uint(b.x), __float_as_uint(b.y));
            }
        }

        // ---- scores + bias -> E ----
#pragma unroll
        for (int nt = 0; nt < 4; nt++) {
            int j0 = (wh * 4 + nt) * 8 + 2 * tt;
            float k0 = sm.knp[bi][j0], k1 = sm.knp[bi][j0 + 1];
            int l0 = sm.jli[bi][j0], l1 = sm.jli[bi][j0 + 1];
            float rA0 = fmaxf(qnA + k0 - 2.f * c[nt][0], 0.f) + __bfloat162float(sm.ldp[l0 + yvA]);
            float rA1 = fmaxf(qnA + k1 - 2.f * c[nt][1], 0.f) + __bfloat162float(sm.ldp[l1 + yvA]);
            float rB0 = fmaxf(qnB + k0 - 2.f * c[nt][2], 0.f) + __bfloat162float(sm.ldp[l0 + yvB]);
            float rB1 = fmaxf(qnB + k1 - 2.f * c[nt][3], 0.f) + __bfloat162float(sm.ldp[l1 + yvB]);
            float eA0 = tf32r(__expf(-rA0));
            float eA1 = tf32r(__expf(-rA1));
            float eB0 = tf32r(__expf(-rB0));
            float eB1 = tf32r(__expf(-rB1));
            denA += eA0 + eA1; denB += eB0 + eB1;
            *(float2*)&sm.Es[qA][j0] = make_float2(eA0, eA1);
            *(float2*)&sm.Es[qB][j0] = make_float2(eB0, eB1);
        }
        __syncthreads();

        // ---- EV: warp covers V cols [wh*16, wh*16+16), all 64 j ----
#pragma unroll
        for (int ekt = 0; ekt < 8; ekt++) {
            uint32_t a0 = *(const uint32_t*)&sm.Es[qA][ekt * 8 + tt];
            uint32_t a1 = *(const uint32_t*)&sm.Es[qB][ekt * 8 + tt];
            uint32_t a2 = *(const uint32_t*)&sm.Es[qA][ekt * 8 + tt + 4];
            uint32_t a3 = *(const uint32_t*)&sm.Es[qB][ekt * 8 + tt + 4];
#pragma unroll
            for (int nt2 = 0; nt2 < 2; nt2++) {
                float2 b = *(const float2*)&sm.VTs[bi][(wh * 2 + nt2) * 8 + g][ekt * 8 + 2 * tt];
                mma_tf32(C2[nt2], a0, a1, a2, a3, __float_as_uint(b.x), __float_as_uint(b.y));
            }
        }
    }

    // ---- epilogue ----
    float* outb = g_out2 + (size_t)z * B * 32;
#pragma unroll
    for (int nt2 = 0; nt2 < 2; nt2++) {
        int col = (wh * 2 + nt2) * 8 + 2 * tt;
        atomicAdd(outb + (size_t)(qbase + qA) * 32 + col,     C2[nt2][0]);
        atomicAdd(outb + (size_t)(qbase + qA) * 32 + col + 1, C2[nt2][1]);
        atomicAdd(outb + (size_t)(qbase + qB) * 32 + col,     C2[nt2][2]);
        atomicAdd(outb + (size_t)(qbase + qB) * 32 + col + 1, C2[nt2][3]);
    }
    denA += __shfl_xor_sync(0xffffffffu, denA, 1);
    denA += __shfl_xor_sync(0xffffffffu, denA, 2);
    denB += __shfl_xor_sync(0xffffffffu, denB, 1);
    denB += __shfl_xor_sync(0xffffffffu, denB, 2);
    if (tt == 0) {
        atomicAdd(&g_den2[(size_t)z * B + qbase + qA], denA);
        atomicAdd(&g_den2[(size_t)z * B + qbase + qB], denB);
    }
}

// ---------------- final ----------------
__global__ void final_kernel(float* __restrict__ out, int B, int DY) {
    int idx = blockIdx.x * blockDim.x + threadIdx.x;
    if (idx >= B * DY) return;
    int b = idx >> 5;
    out[idx] = 0.5f * (g_out2[idx] / g_den2[b] + g_out2[(size_t)B * 32 + idx] / g_den2[B + b]);
}

// ---------------- launch ----------------
extern "C" void kernel_launch(void* const* d_in, const int* in_sizes, int n_in,
                              void* d_out, int out_size) {
    const float* x   = (const float*)d_in[0];
    const float* sf  = (const float*)d_in[1];
    const float* sl  = (const float*)d_in[2];
    const float* f1  = (const float*)d_in[3];
    const float* f2  = (const float*)d_in[4];
    const float* u1  = (const float*)d_in[5];
    const float* u2  = (const float*)d_in[6];
    const float* ld1 = (const float*)d_in[7];
    const float* ld2 = (const float*)d_in[8];
    const float* W1  = (const float*)d_in[9];
    const float* b1  = (const float*)d_in[10];
    const float* W2  = (const float*)d_in[11];
    const float* b2  = (const float*)d_in[12];
    const int*   li1 = (const int*)d_in[13];
    const int*   li2 = (const int*)d_in[14];

    int DY = in_sizes[10];            // 32
    int Dd = in_sizes[9] / DY;        // 64
    int B  = in_sizes[0] / Dd;        // 2048
    int N  = in_sizes[1] / Dd;        // 20000
    int L  = in_sizes[5] / DY;        // 100

    int ntiles = NPAD / 64;                           // 313
    int chunk1 = ((ntiles + NS1 - 1) / NS1) * 64;
    int chunk2 = ((ntiles + NS2 - 1) / NS2) * 64;

    cudaFuncSetAttribute(pass1_kernel, cudaFuncAttributeMaxDynamicSharedMemorySize, (int)sizeof(SmP1));
    cudaFuncSetAttribute(pass2_kernel, cudaFuncAttributeMaxDynamicSharedMemorySize, (int)sizeof(SmP2));

    init_kernel<<<(B * 64 + 255) / 256, 256>>>(B);
    cvt32_kernel<<<(3 * NPAD + MAXB + 255) / 256, 256>>>(x, sf, f1, f2, B, N);
    cvtT32_kernel<<<dim3(NPAD / 32, 5), dim3(32, 8)>>>(f1, f2, sl, N);
    cvtldt_kernel<<<(NPAD + 255) / 256, 256>>>(ld1, ld2, li1, li2, N, L);

    pass1_kernel<<<dim3(B / 128, NS1), 512, sizeof(SmP1)>>>(B, N, chunk1);

    mid_kernel<<<B / 8, 256>>>(f1, f2, W1, b1, W2, b2, u1, u2, B, N, DY, L);

    pass2_kernel<<<dim3(B / 128, NS2, 2), 512, sizeof(SmP2)>>>(B, N, L, chunk2);

    final_kernel<<<(B * DY + 255) / 256, 256>>>((float*)d_out, B, DY);
}

// round 15
// speedup vs baseline: 1.0850x; 1.0850x over previous
#include <cuda_runtime.h>
#include <cuda_bf16.h>
#include <cstdint>

#define NPAD 20032
#define MAXB 2048
#define MAXN 20000
#define MAXL 100
#define NS1  9
#define NS2  4
#define RS   72   // smem row stride in floats; RS%32==8 -> conflict-free float2 frags

// ---------------- static device scratch (tf32-rounded; contraction dims k-permuted) ----------------
__device__ __align__(16) float g_x32[MAXB * 64];
__device__ __align__(16) float g_sf32[NPAD * 64];
__device__ __align__(16) float g_f132[NPAD * 64];
__device__ __align__(16) float g_f232[NPAD * 64];
__device__ __align__(16) float g_V32[(size_t)128 * NPAD];   // [c][i-perm]
__device__ __align__(16) float g_slT32[(size_t)32 * NPAD];  // [c][i-perm]
__device__ __align__(16) float g_xt321[MAXB * 64];
__device__ __align__(16) float g_xt322[MAXB * 64];
__device__ __align__(16) __nv_bfloat16 g_ldtb[2 * MAXL * MAXL];
__device__ __align__(16) float g_xnorm[MAXB];
__device__ __align__(16) float g_snorm[NPAD];    // padded with 1e4
__device__ __align__(16) float g_f1norm[NPAD];
__device__ __align__(16) float g_f2norm[NPAD];
__device__ __align__(16) int   g_li1p[NPAD];
__device__ __align__(16) int   g_li2p[NPAD];
__device__ int   g_match[MAXB];
__device__ float g_acc1[MAXB * 64];
__device__ float g_acc2[MAXB * 64];
__device__ float g_den[MAXB];
__device__ float g_xtn1[MAXB];
__device__ float g_xtn2[MAXB];
__device__ int   g_yidx1[MAXB];
__device__ int   g_yidx2[MAXB];
__device__ float g_out2[2 * MAXB * 32];
__device__ float g_den2[2 * MAXB];

// ---------------- helpers ----------------
__device__ __forceinline__ uint32_t saddr(const void* p) {
    return (uint32_t)__cvta_generic_to_shared(p);
}
__device__ __forceinline__ void cpa16(uint32_t dst, const void* src) {
    asm volatile("cp.async.cg.shared.global [%0], [%1], 16;" :: "r"(dst), "l"(src));
}
__device__ __forceinline__ void cpa_commit() {
    asm volatile("cp.async.commit_group;" ::: "memory");
}
__device__ __forceinline__ void cpa_wait0() {
    asm volatile("cp.async.wait_group 0;" ::: "memory");
}
__device__ __forceinline__ float tf32r(float f) {
    uint32_t u; asm("cvt.rna.tf32.f32 %0, %1;" : "=r"(u) : "f"(f));
    return __uint_as_float(u);
}
__device__ __forceinline__ void mma_tf32(float* c, uint32_t a0, uint32_t a1, uint32_t a2, uint32_t a3,
                                         uint32_t b0, uint32_t b1) {
    asm volatile("mma.sync.aligned.m16n8k8.row.col.f32.tf32.tf32.f32 "
                 "{%0,%1,%2,%3}, {%4,%5,%6,%7}, {%8,%9}, {%0,%1,%2,%3};"
                 : "+f"(c[0]), "+f"(c[1]), "+f"(c[2]), "+f"(c[3])
                 : "r"(a0), "r"(a1), "r"(a2), "r"(a3), "r"(b0), "r"(b1));
}
// permuted position of logical index k within its 8-group: order 0,4,1,5,2,6,3,7
__device__ __forceinline__ int kperm(int k) {
    return (k & ~7) | (((k & 3) << 1) | ((k >> 2) & 1));
}

// ---------------- prep kernels ----------------
__global__ void init_kernel(int B) {
    int i = blockIdx.x * 256 + threadIdx.x;
    if (i < B * 64) { g_acc1[i] = 0.f; g_acc2[i] = 0.f; }
    if (i < 2 * B * 32) g_out2[i] = 0.f;
    if (i < B) {
        g_den[i] = 0.f; g_match[i] = 0x7fffffff;
        g_den2[i] = 0.f; g_den2[B + i] = 0.f;
    }
}

__global__ void cvt32_kernel(const float* __restrict__ x, const float* __restrict__ sf,
                             const float* __restrict__ f1, const float* __restrict__ f2,
                             int B, int N) {
    int r = blockIdx.x * blockDim.x + threadIdx.x;
    const float* src; float* dst; float* ndst; int row, nrow;
    if (r < NPAD)          { src = sf; dst = g_sf32; ndst = g_snorm;  row = r;            nrow = N; }
    else if (r < 2 * NPAD) { src = f1; dst = g_f132; ndst = g_f1norm; row = r - NPAD;     nrow = N; }
    else if (r < 3 * NPAD) { src = f2; dst = g_f232; ndst = g_f2norm; row = r - 2 * NPAD; nrow = N; }
    else                   { src = x;  dst = g_x32;  ndst = g_xnorm;  row = r - 3 * NPAD; nrow = B;
                             if (row >= B) return; }
    bool ok = row < nrow;
    float s = 0.f;
#pragma unroll
    for (int kk = 0; kk < 8; kk++) {
        float4 v0 = ok ? ((const float4*)(src + (size_t)row * 64))[2 * kk]     : make_float4(0.f, 0.f, 0.f, 0.f);
        float4 v1 = ok ? ((const float4*)(src + (size_t)row * 64))[2 * kk + 1] : make_float4(0.f, 0.f, 0.f, 0.f);
        float a0 = tf32r(v0.x), a1 = tf32r(v0.y), a2 = tf32r(v0.z), a3 = tf32r(v0.w);
        float a4 = tf32r(v1.x), a5 = tf32r(v1.y), a6 = tf32r(v1.z), a7 = tf32r(v1.w);
        ((float4*)(dst + (size_t)row * 64))[2 * kk]     = make_float4(a0, a4, a1, a5);
        ((float4*)(dst + (size_t)row * 64))[2 * kk + 1] = make_float4(a2, a6, a3, a7);
        s = fmaf(a0, a0, fmaf(a1, a1, fmaf(a2, a2, fmaf(a3, a3, s))));
        s = fmaf(a4, a4, fmaf(a5, a5, fmaf(a6, a6, fmaf(a7, a7, s))));
    }
    ndst[row] = ok ? s : 1e4f;
}

__global__ void cvtT32_kernel(const float* __restrict__ f1, const float* __restrict__ f2,
                              const float* __restrict__ sl, int N) {
    __shared__ float tile[32][33];
    int combo = blockIdx.y;
    int i0 = blockIdx.x * 32;
    const float* src; float* dst; int d0, ncol, outrow0;
    if (combo < 2)      { src = f1; dst = g_V32;   d0 = combo * 32;       ncol = 64; outrow0 = d0; }
    else if (combo < 4) { src = f2; dst = g_V32;   d0 = (combo - 2) * 32; ncol = 64; outrow0 = 64 + d0; }
    else                { src = sl; dst = g_slT32; d0 = 0;                ncol = 32; outrow0 = 0; }
    int txx = threadIdx.x, tyy = threadIdx.y;
#pragma unroll
    for (int r = tyy; r < 32; r += 8) {
        int i = i0 + r;
        tile[r][txx] = (i < N) ? src[(size_t)i * ncol + d0 + txx] : 0.f;
    }
    __syncthreads();
#pragma unroll
    for (int rr = tyy; rr < 32; rr += 8)
        dst[(size_t)(outrow0 + rr) * NPAD + i0 + kperm(txx)] = tf32r(tile[txx][rr]);
}

__global__ void cvtldt_kernel(const float* __restrict__ ld1, const float* __restrict__ ld2,
                              const int* __restrict__ li1, const int* __restrict__ li2,
                              int N, int L) {
    int i = blockIdx.x * 256 + threadIdx.x;
    if (i < L * L) {
        g_ldtb[i] = __float2bfloat16(0.01f * ld1[i]);
        g_ldtb[MAXL * MAXL + i] = __float2bfloat16(0.01f * ld2[i]);
    }
    if (i < NPAD) {
        g_li1p[i] = (i < N) ? li1[i] * L : 0;
        g_li2p[i] = (i < N) ? li2[i] * L : 0;
    }
}

// dummy: shifts pass1 to launch #6 so ncu (-s 5 -c 1) captures it
__global__ void dummy_kernel() {}

// ---------------- Pass 1 (tf32 HMMA, double-buffered, LDS.64 frags) ----------------
struct __align__(16) SmP1 {
    float Qs[128][RS];
    float Es[128][RS];     // E is UNpermuted (store layout == load layout cancels)
    float Ks[2][64][RS];
    float VTs[2][128][RS];
    float knp[2][64];
};

__global__ void __launch_bounds__(256, 1) pass1_kernel(int B, int N, int chunk) {
    extern __shared__ char smraw[];
    SmP1& sm = *reinterpret_cast<SmP1*>(smraw);
    int t = threadIdx.x, w = t >> 5, lane = t & 31, g = lane >> 2, tt = lane & 3;
    int qbase = blockIdx.x * 128;
    int i0base = blockIdx.y * chunk;
    int iend = min(i0base + chunk, NPAD);
    int ntl = (iend - i0base) >> 6;
    int qA = w * 16 + g, qB = qA + 8;
    float qnA = g_xnorm[qbase + qA], qnB = g_xnorm[qbase + qB];

#pragma unroll
    for (int k = 0; k < 8; k++) {
        int gc = t + 256 * k, row = gc >> 4, ch = gc & 15;
        cpa16(saddr(&sm.Qs[row][ch * 4]), g_x32 + (size_t)(qbase + row) * 64 + ch * 4);
    }
#define P1_LOAD(i0v, bi)                                                                   \
    {                                                                                      \
        _Pragma("unroll") for (int k = 0; k < 4; k++) {                                    \
            int gc = t + 256 * k, row = gc >> 4, ch = gc & 15;                             \
            cpa16(saddr(&sm.Ks[bi][row][ch * 4]), g_sf32 + (size_t)((i0v) + row) * 64 + ch * 4); } \
        _Pragma("unroll") for (int k = 0; k < 8; k++) {                                    \
            int gc = t + 256 * k, row = gc >> 4, ch = gc & 15;                             \
            cpa16(saddr(&sm.VTs[bi][row][ch * 4]), g_V32 + (size_t)row * NPAD + (i0v) + ch * 4); } \
        if (t < 16) cpa16(saddr(&sm.knp[bi][t * 4]), g_snorm + (i0v) + t * 4);             \
        cpa_commit();                                                                      \
    }
    P1_LOAD(i0base, 0);

    float C2[16][4];
#pragma unroll
    for (int a = 0; a < 16; a++) { C2[a][0] = 0.f; C2[a][1] = 0.f; C2[a][2] = 0.f; C2[a][3] = 0.f; }
    float denA = 0.f, denB = 0.f;
    int mmA = 0x7fffffff, mmB = 0x7fffffff;

    for (int it = 0; it < ntl; it++) {
        int bi = it & 1;
        int i0 = i0base + it * 64;
        cpa_wait0();
        __syncthreads();
        if (it + 1 < ntl) P1_LOAD(i0 + 64, bi ^ 1);

        // ---- QK (float2 fragment loads from permuted layout) ----
        float c[8][4];
#pragma unroll
        for (int a = 0; a < 8; a++) { c[a][0] = 0.f; c[a][1] = 0.f; c[a][2] = 0.f; c[a][3] = 0.f; }
#pragma unroll
        for (int kt = 0; kt < 8; kt++) {
            float2 aA = *(const float2*)&sm.Qs[qA][kt * 8 + 2 * tt];
            float2 aB = *(const float2*)&sm.Qs[qB][kt * 8 + 2 * tt];
            uint32_t a0 = __float_as_uint(aA.x), a1 = __float_as_uint(aB.x);
            uint32_t a2 = __float_as_uint(aA.y), a3 = __float_as_uint(aB.y);
#pragma unroll
            for (int nt = 0; nt < 8; nt++) {
                float2 b = *(const float2*)&sm.Ks[bi][nt * 8 + g][kt * 8 + 2 * tt];
                mma_tf32(c[nt], a0, a1, a2, a3, __float_as_uint(b.x), __float_as_uint(b.y));
            }
        }

        // ---- scores -> E (unpermuted) ----
#pragma unroll
        for (int nt = 0; nt < 8; nt++) {
            int j0 = nt * 8 + 2 * tt;
            float k0 = sm.knp[bi][j0], k1 = sm.knp[bi][j0 + 1];
            float rA0 = qnA + k0 - 2.f * c[nt][0];
            float rA1 = qnA + k1 - 2.f * c[nt][1];
            float rB0 = qnB + k0 - 2.f * c[nt][2];
            float rB1 = qnB + k1 - 2.f * c[nt][3];
            if (rA0 <= 2e-4f) mmA = min(mmA, i0 + j0);
            if (rA1 <= 2e-4f) mmA = min(mmA, i0 + j0 + 1);
            if (rB0 <= 2e-4f) mmB = min(mmB, i0 + j0);
            if (rB1 <= 2e-4f) mmB = min(mmB, i0 + j0 + 1);
            float eA0 = tf32r(__expf(-fmaxf(rA0, 0.f)));
            float eA1 = tf32r(__expf(-fmaxf(rA1, 0.f)));
            float eB0 = tf32r(__expf(-fmaxf(rB0, 0.f)));
            float eB1 = tf32r(__expf(-fmaxf(rB1, 0.f)));
            denA += eA0 + eA1; denB += eB0 + eB1;
            *(float2*)&sm.Es[qA][j0] = make_float2(eA0, eA1);
            *(float2*)&sm.Es[qB][j0] = make_float2(eB0, eB1);
        }
        __syncwarp();

        // ---- EV (E scalar loads, V float2 loads) ----
#pragma unroll
        for (int ekt = 0; ekt < 8; ekt++) {
            uint32_t a0 = *(const uint32_t*)&sm.Es[qA][ekt * 8 + tt];
            uint32_t a1 = *(const uint32_t*)&sm.Es[qB][ekt * 8 + tt];
            uint32_t a2 = *(const uint32_t*)&sm.Es[qA][ekt * 8 + tt + 4];
            uint32_t a3 = *(const uint32_t*)&sm.Es[qB][ekt * 8 + tt + 4];
#pragma unroll
            for (int nt2 = 0; nt2 < 16; nt2++) {
                float2 b = *(const float2*)&sm.VTs[bi][nt2 * 8 + g][ekt * 8 + 2 * tt];
                mma_tf32(C2[nt2], a0, a1, a2, a3, __float_as_uint(b.x), __float_as_uint(b.y));
            }
        }
    }

    // ---- epilogue ----
#pragma unroll
    for (int nt2 = 0; nt2 < 16; nt2++) {
        int col = nt2 * 8 + 2 * tt;
        float* base = (col < 64) ? g_acc1 : g_acc2;
        int cc = col & 63;
        atomicAdd(base + (size_t)(qbase + qA) * 64 + cc,     C2[nt2][0]);
        atomicAdd(base + (size_t)(qbase + qA) * 64 + cc + 1, C2[nt2][1]);
        atomicAdd(base + (size_t)(qbase + qB) * 64 + cc,     C2[nt2][2]);
        atomicAdd(base + (size_t)(qbase + qB) * 64 + cc + 1, C2[nt2][3]);
    }
    denA += __shfl_xor_sync(0xffffffffu, denA, 1);
    denA += __shfl_xor_sync(0xffffffffu, denA, 2);
    denB += __shfl_xor_sync(0xffffffffu, denB, 1);
    denB += __shfl_xor_sync(0xffffffffu, denB, 2);
    mmA = min(mmA, __shfl_xor_sync(0xffffffffu, mmA, 1));
    mmA = min(mmA, __shfl_xor_sync(0xffffffffu, mmA, 2));
    mmB = min(mmB, __shfl_xor_sync(0xffffffffu, mmB, 1));
    mmB = min(mmB, __shfl_xor_sync(0xffffffffu, mmB, 2));
    if (tt == 0) {
        atomicAdd(&g_den[qbase + qA], denA);
        atomicAdd(&g_den[qbase + qB], denB);
        if (mmA != 0x7fffffff) atomicMin(&g_match[qbase + qA], mmA);
        if (mmB != 0x7fffffff) atomicMin(&g_match[qbase + qB], mmB);
    }
}

// ---------------- mid ----------------
__global__ void mid_kernel(const float* __restrict__ f1, const float* __restrict__ f2,
                           const float* __restrict__ W1, const float* __restrict__ b1,
                           const float* __restrict__ W2, const float* __restrict__ b2,
                           const float* __restrict__ u1, const float* __restrict__ u2,
                           int B, int N, int DY, int L) {
    __shared__ float sxt[8][2][64];
    __shared__ float sy[8][2][32];
    int wl = threadIdx.x >> 5;
    int lane = threadIdx.x & 31;
    int b = blockIdx.x * 8 + wl;
    if (b >= B) return;

    float inv = 1.0f / g_den[b];
    int d0 = lane, d1 = lane + 32;
    float x10 = g_acc1[(size_t)b * 64 + d0] * inv;
    float x11 = g_acc1[(size_t)b * 64 + d1] * inv;
    float x20 = g_acc2[(size_t)b * 64 + d0] * inv;
    float x21 = g_acc2[(size_t)b * 64 + d1] * inv;
    int m = g_match[b];
    if (m < N) {
        x10 = f1[(size_t)m * 64 + d0]; x11 = f1[(size_t)m * 64 + d1];
        x20 = f2[(size_t)m * 64 + d0]; x21 = f2[(size_t)m * 64 + d1];
    }
    float r10 = tf32r(x10), r11 = tf32r(x11), r20 = tf32r(x20), r21 = tf32r(x21);
    int p0 = kperm(d0), p1 = kperm(d1);
    g_xt321[b * 64 + p0] = r10; g_xt321[b * 64 + p1] = r11;
    g_xt322[b * 64 + p0] = r20; g_xt322[b * 64 + p1] = r21;
    sxt[wl][0][d0] = x10; sxt[wl][0][d1] = x11;
    sxt[wl][1][d0] = x20; sxt[wl][1][d1] = x21;
    float nr1 = r10 * r10 + r11 * r11;
    float nr2 = r20 * r20 + r21 * r21;
#pragma unroll
    for (int o = 16; o; o >>= 1) {
        nr1 += __shfl_xor_sync(0xffffffffu, nr1, o);
        nr2 += __shfl_xor_sync(0xffffffffu, nr2, o);
    }
    if (lane == 0) { g_xtn1[b] = nr1; g_xtn2[b] = nr2; }
    __syncwarp();

    if (lane < DY) {
        float y1 = b1[lane], y2 = b2[lane];
#pragma unroll
        for (int d = 0; d < 64; d++) {
            y1 = fmaf(sxt[wl][0][d], W1[d * DY + lane], y1);
            y2 = fmaf(sxt[wl][1][d], W2[d * DY + lane], y2);
        }
        sy[wl][0][lane] = y1; sy[wl][1][lane] = y2;
    }
    __syncwarp();

    float best1 = 1e38f, best2 = 1e38f; int bi1 = 0x7fffffff, bi2 = 0x7fffffff;
    for (int lab = lane; lab < L; lab += 32) {
        float s1 = 0.f, s2 = 0.f;
        for (int dy = 0; dy < DY; dy++) {
            float t1 = sy[wl][0][dy] - u1[lab * DY + dy]; s1 = fmaf(t1, t1, s1);
            float t2 = sy[wl][1][dy] - u2[lab * DY + dy]; s2 = fmaf(t2, t2, s2);
        }
        if (s1 < best1) { best1 = s1; bi1 = lab; }
        if (s2 < best2) { best2 = s2; bi2 = lab; }
    }
#pragma unroll
    for (int o = 16; o; o >>= 1) {
        float ob = __shfl_xor_sync(0xffffffffu, best1, o);
        int obi  = __shfl_xor_sync(0xffffffffu, bi1, o);
        if (ob < best1 || (ob == best1 && obi < bi1)) { best1 = ob; bi1 = obi; }
        ob  = __shfl_xor_sync(0xffffffffu, best2, o);
        obi = __shfl_xor_sync(0xffffffffu, bi2, o);
        if (ob < best2 || (ob == best2 && obi < bi2)) { best2 = ob; bi2 = obi; }
    }
    if (lane == 0) { g_yidx1[b] = bi1; g_yidx2[b] = bi2; }
}

// ---------------- Pass 2 (tf32 HMMA, 64-q CTAs, 128 threads, 2 CTAs/SM) ----------------
struct __align__(16) SmP2 {
    float Qs[64][RS];
    float Es[64][RS];
    float Ks[2][64][RS];
    float VTs[2][32][RS];
    float knp[2][64];
    int   jli[2][64];
    __nv_bfloat16 ldp[MAXL * MAXL];
};

__global__ void __launch_bounds__(128, 2) pass2_kernel(int B, int N, int L, int chunk) {
    extern __shared__ char smraw[];
    SmP2& sm = *reinterpret_cast<SmP2*>(smraw);
    int t = threadIdx.x, w = t >> 5, lane = t & 31, g = lane >> 2, tt = lane & 3;
    int z = blockIdx.z;
    const float* Qg = z ? g_xt322 : g_xt321;
    const float* Kg = z ? g_f232 : g_f132;
    const float* kng = z ? g_f2norm : g_f1norm;
    const float* qng = z ? g_xtn2 : g_xtn1;
    const int* lip = z ? g_li2p : g_li1p;
    const int* yix = z ? g_yidx2 : g_yidx1;

    int qbase = blockIdx.x * 64;
    int i0base = blockIdx.y * chunk;
    int iend = min(i0base + chunk, NPAD);
    int ntl = (iend - i0base) >> 6;
    int qA = w * 16 + g, qB = qA + 8;
    float qnA = qng[qbase + qA], qnB = qng[qbase + qB];
    int yvA = yix[qbase + qA], yvB = yix[qbase + qB];

    // Q tile: 64 rows x 16 chunks = 1024, 128 thr -> 8 each
#pragma unroll
    for (int k = 0; k < 8; k++) {
        int gc = t + 128 * k, row = gc >> 4, ch = gc & 15;
        cpa16(saddr(&sm.Qs[row][ch * 4]), Qg + (size_t)(qbase + row) * 64 + ch * 4);
    }
    // ldp: 1250 chunks -> 10 each
#pragma unroll
    for (int k = 0; k < 10; k++) {
        int gc = t + 128 * k;
        if (gc < 1250)
            cpa16(saddr((char*)sm.ldp + gc * 16),
                  (const char*)(g_ldtb + (size_t)z * MAXL * MAXL) + gc * 16);
    }
#define P2_LOAD(i0v, bi)                                                                   \
    {                                                                                      \
        _Pragma("unroll") for (int k = 0; k < 8; k++) {                                    \
            int gc = t + 128 * k, row = gc >> 4, ch = gc & 15;                             \
            cpa16(saddr(&sm.Ks[bi][row][ch * 4]), Kg + (size_t)((i0v) + row) * 64 + ch * 4); } \
        _Pragma("unroll") for (int k = 0; k < 4; k++) {                                    \
            int gc = t + 128 * k, row = gc >> 4, ch = gc & 15;                             \
            cpa16(saddr(&sm.VTs[bi][row][ch * 4]), g_slT32 + (size_t)row * NPAD + (i0v) + ch * 4); } \
        if (t < 16) cpa16(saddr(&sm.knp[bi][t * 4]), kng + (i0v) + t * 4);                 \
        else if (t < 32) cpa16(saddr(&sm.jli[bi][(t - 16) * 4]), lip + (i0v) + (t - 16) * 4); \
        cpa_commit();                                                                      \
    }
    P2_LOAD(i0base, 0);

    float C2[4][4];
#pragma unroll
    for (int a = 0; a < 4; a++) { C2[a][0] = 0.f; C2[a][1] = 0.f; C2[a][2] = 0.f; C2[a][3] = 0.f; }
    float denA = 0.f, denB = 0.f;

    for (int it = 0; it < ntl; it++) {
        int bi = it & 1;
        cpa_wait0();
        __syncthreads();
        if (it + 1 < ntl) P2_LOAD(i0base + (it + 1) * 64, bi ^ 1);

        // ---- QK ----
        float c[8][4];
#pragma unroll
        for (int a = 0; a < 8; a++) { c[a][0] = 0.f; c[a][1] = 0.f; c[a][2] = 0.f; c[a][3] = 0.f; }
#pragma unroll
        for (int kt = 0; kt < 8; kt++) {
            float2 aA = *(const float2*)&sm.Qs[qA][kt * 8 + 2 * tt];
            float2 aB = *(const float2*)&sm.Qs[qB][kt * 8 + 2 * tt];
            uint32_t a0 = __float_as_uint(aA.x), a1 = __float_as_uint(aB.x);
            uint32_t a2 = __float_as_uint(aA.y), a3 = __float_as_uint(aB.y);
#pragma unroll
            for (int nt = 0; nt < 8; nt++) {
                float2 b = *(const float2*)&sm.Ks[bi][nt * 8 + g][kt * 8 + 2 * tt];
                mma_tf32(c[nt], a0, a1, a2, a3, __float_as_uint(b.x), __float_as_uint(b.y));
            }
        }

        // ---- scores + bias -> E ----
#pragma unroll
        for (int nt = 0; nt < 8; nt++) {
            int j0 = nt * 8 + 2 * tt;
            float k0 = sm.knp[bi][j0], k1 = sm.knp[bi][j0 + 1];
            int l0 = sm.jli[bi][j0], l1 = sm.jli[bi][j0 + 1];
            float rA0 = fmaxf(qnA + k0 - 2.f * c[nt][0], 0.f) + __bfloat162float(sm.ldp[l0 + yvA]);
            float rA1 = fmaxf(qnA + k1 - 2.f * c[nt][1], 0.f) + __bfloat162float(sm.ldp[l1 + yvA]);
            float rB0 = fmaxf(qnB + k0 - 2.f * c[nt][2], 0.f) + __bfloat162float(sm.ldp[l0 + yvB]);
            float rB1 = fmaxf(qnB + k1 - 2.f * c[nt][3], 0.f) + __bfloat162float(sm.ldp[l1 + yvB]);
            float eA0 = tf32r(__expf(-rA0));
            float eA1 = tf32r(__expf(-rA1));
            float eB0 = tf32r(__expf(-rB0));
            float eB1 = tf32r(__expf(-rB1));
            denA += eA0 + eA1; denB += eB0 + eB1;
            *(float2*)&sm.Es[qA][j0] = make_float2(eA0, eA1);
            *(float2*)&sm.Es[qB][j0] = make_float2(eB0, eB1);
        }
        __syncwarp();   // E rows qA/qB warp-private (4 warps x 16 q = 64 q)

        // ---- EV ----
#pragma unroll
        for (int ekt = 0; ekt < 8; ekt++) {
            uint32_t a0 = *(const uint32_t*)&sm.Es[qA][ekt * 8 + tt];
            uint32_t a1 = *(const uint32_t*)&sm.Es[qB][ekt * 8 + tt];
            uint32_t a2 = *(const uint32_t*)&sm.Es[qA][ekt * 8 + tt + 4];
            uint32_t a3 = *(const uint32_t*)&sm.Es[qB][ekt * 8 + tt + 4];
#pragma unroll
            for (int nt2 = 0; nt2 < 4; nt2++) {
                float2 b = *(const float2*)&sm.VTs[bi][nt2 * 8 + g][ekt * 8 + 2 * tt];
                mma_tf32(C2[nt2], a0, a1, a2, a3, __float_as_uint(b.x), __float_as_uint(b.y));
            }
        }
    }

    // ---- epilogue ----
    float* outb = g_out2 + (size_t)z * B * 32;
#pragma unroll
    for (int nt2 = 0; nt2 < 4; nt2++) {
        int col = nt2 * 8 + 2 * tt;
        atomicAdd(outb + (size_t)(qbase + qA) * 32 + col,     C2[nt2][0]);
        atomicAdd(outb + (size_t)(qbase + qA) * 32 + col + 1, C2[nt2][1]);
        atomicAdd(outb + (size_t)(qbase + qB) * 32 + col,     C2[nt2][2]);
        atomicAdd(outb + (size_t)(qbase + qB) * 32 + col + 1, C2[nt2][3]);
    }
    denA += __shfl_xor_sync(0xffffffffu, denA, 1);
    denA += __shfl_xor_sync(0xffffffffu, denA, 2);
    denB += __shfl_xor_sync(0xffffffffu, denB, 1);
    denB += __shfl_xor_sync(0xffffffffu, denB, 2);
    if (tt == 0) {
        atomicAdd(&g_den2[(size_t)z * B + qbase + qA], denA);
        atomicAdd(&g_den2[(size_t)z * B + qbase + qB], denB);
    }
}

// ---------------- final ----------------
__global__ void final_kernel(float* __restrict__ out, int B, int DY) {
    int idx = blockIdx.x * blockDim.x + threadIdx.x;
    if (idx >= B * DY) return;
    int b = idx >> 5;
    out[idx] = 0.5f * (g_out2[idx] / g_den2[b] + g_out2[(size_t)B * 32 + idx] / g_den2[B + b]);
}

// ---------------- launch ----------------
extern "C" void kernel_launch(void* const* d_in, const int* in_sizes, int n_in,
                              void* d_out, int out_size) {
    const float* x   = (const float*)d_in[0];
    const float* sf  = (const float*)d_in[1];
    const float* sl  = (const float*)d_in[2];
    const float* f1  = (const float*)d_in[3];
    const float* f2  = (const float*)d_in[4];
    const float* u1  = (const float*)d_in[5];
    const float* u2  = (const float*)d_in[6];
    const float* ld1 = (const float*)d_in[7];
    const float* ld2 = (const float*)d_in[8];
    const float* W1  = (const float*)d_in[9];
    const float* b1  = (const float*)d_in[10];
    const float* W2  = (const float*)d_in[11];
    const float* b2  = (const float*)d_in[12];
    const int*   li1 = (const int*)d_in[13];
    const int*   li2 = (const int*)d_in[14];

    int DY = in_sizes[10];            // 32
    int Dd = in_sizes[9] / DY;        // 64
    int B  = in_sizes[0] / Dd;        // 2048
    int N  = in_sizes[1] / Dd;        // 20000
    int L  = in_sizes[5] / DY;        // 100

    int ntiles = NPAD / 64;                           // 313
    int chunk1 = ((ntiles + NS1 - 1) / NS1) * 64;
    int chunk2 = ((ntiles + NS2 - 1) / NS2) * 64;

    cudaFuncSetAttribute(pass1_kernel, cudaFuncAttributeMaxDynamicSharedMemorySize, (int)sizeof(SmP1));
    cudaFuncSetAttribute(pass2_kernel, cudaFuncAttributeMaxDynamicSharedMemorySize, (int)sizeof(SmP2));

    init_kernel<<<(B * 64 + 255) / 256, 256>>>(B);
    cvt32_kernel<<<(3 * NPAD + MAXB + 255) / 256, 256>>>(x, sf, f1, f2, B, N);
    cvtT32_kernel<<<dim3(NPAD / 32, 5), dim3(32, 8)>>>(f1, f2, sl, N);
    cvtldt_kernel<<<(NPAD + 255) / 256, 256>>>(ld1, ld2, li1, li2, N, L);
    dummy_kernel<<<1, 32>>>();   // shift pass1 to launch #6 (ncu -s 5 -c 1 target)

    pass1_kernel<<<dim3(B / 128, NS1), 256, sizeof(SmP1)>>>(B, N, chunk1);

    mid_kernel<<<B / 8, 256>>>(f1, f2, W1, b1, W2, b2, u1, u2, B, N, DY, L);

    pass2_kernel<<<dim3(B / 64, NS2, 2), 128, sizeof(SmP2)>>>(B, N, L, chunk2);

    final_kernel<<<(B * DY + 255) / 256, 256>>>((float*)d_out, B, DY);
}

// round 16
// speedup vs baseline: 1.7545x; 1.6171x over previous
#include <cuda_runtime.h>
#include <cuda_fp16.h>
#include <cuda_bf16.h>
#include <cstdint>

#define NPAD 20032
#define MAXB 2048
#define MAXN 20000
#define MAXL 100
#define NS1  18
#define NS2  9
#define RSH  72   // smem row stride in halves (64 data + 8 pad)

// ---------------- static device scratch ----------------
__device__ __align__(16) __half g_xh[MAXB * 64];
__device__ __align__(16) __half g_sfh[NPAD * 64];
__device__ __align__(16) __half g_f1h[NPAD * 64];
__device__ __align__(16) __half g_f2h[NPAD * 64];
__device__ __align__(16) __half g_Vh[(size_t)128 * NPAD];   // [c][i]; c 0-63 f1, 64-127 f2
__device__ __align__(16) __half g_slTh[(size_t)32 * NPAD];  // star_labels^T
__device__ __align__(16) __half g_xth1[MAXB * 64];
__device__ __align__(16) __half g_xth2[MAXB * 64];
__device__ __align__(16) __nv_bfloat16 g_ldtb[2 * MAXL * MAXL];
__device__ __align__(16) float g_xnorm[MAXB];
__device__ __align__(16) float g_snorm[NPAD];    // padded 1e4
__device__ __align__(16) float g_f1norm[NPAD];
__device__ __align__(16) float g_f2norm[NPAD];
__device__ __align__(16) int   g_li1p[NPAD];
__device__ __align__(16) int   g_li2p[NPAD];
__device__ int   g_match[MAXB];
__device__ float g_acc1[MAXB * 64];
__device__ float g_acc2[MAXB * 64];
__device__ float g_den[MAXB];
__device__ float g_xtn1[MAXB];
__device__ float g_xtn2[MAXB];
__device__ int   g_yidx1[MAXB];
__device__ int   g_yidx2[MAXB];
__device__ float g_out2[2 * MAXB * 32];
__device__ float g_den2[2 * MAXB];

// ---------------- helpers ----------------
__device__ __forceinline__ uint32_t saddr(const void* p) {
    return (uint32_t)__cvta_generic_to_shared(p);
}
__device__ __forceinline__ void cpa16(uint32_t dst, const void* src) {
    asm volatile("cp.async.cg.shared.global [%0], [%1], 16;" :: "r"(dst), "l"(src));
}
__device__ __forceinline__ void cpa_commit() {
    asm volatile("cp.async.commit_group;" ::: "memory");
}
__device__ __forceinline__ void cpa_wait0() {
    asm volatile("cp.async.wait_group 0;" ::: "memory");
}
// fp16 mma m16n8k16 row.col, fp32 accum
__device__ __forceinline__ void mma_f16(float* c, uint32_t a0, uint32_t a1, uint32_t a2, uint32_t a3,
                                        uint32_t b0, uint32_t b1) {
    asm volatile("mma.sync.aligned.m16n8k16.row.col.f32.f16.f16.f32 "
                 "{%0,%1,%2,%3}, {%4,%5,%6,%7}, {%8,%9}, {%0,%1,%2,%3};"
                 : "+f"(c[0]), "+f"(c[1]), "+f"(c[2]), "+f"(c[3])
                 : "r"(a0), "r"(a1), "r"(a2), "r"(a3), "r"(b0), "r"(b1));
}
// pack 2 floats -> f16x2 reg, lo in bits[15:0]
__device__ __forceinline__ uint32_t h2(float lo, float hi) {
    uint32_t r; asm("cvt.rn.f16x2.f32 %0, %1, %2;" : "=r"(r) : "f"(hi), "f"(lo)); return r;
}
__device__ __forceinline__ float h16r(float f) {   // round through fp16
    return __half2float(__float2half_rn(f));
}

// ---------------- prep kernels ----------------
__global__ void init_kernel(int B) {
    int i = blockIdx.x * 256 + threadIdx.x;
    if (i < B * 64) { g_acc1[i] = 0.f; g_acc2[i] = 0.f; }
    if (i < 2 * B * 32) g_out2[i] = 0.f;
    if (i < B) {
        g_den[i] = 0.f; g_match[i] = 0x7fffffff;
        g_den2[i] = 0.f; g_den2[B + i] = 0.f;
    }
}

// rows -> fp16; norms of fp16-ROUNDED values; pad rows norm 1e4
__global__ void cvth_kernel(const float* __restrict__ x, const float* __restrict__ sf,
                            const float* __restrict__ f1, const float* __restrict__ f2,
                            int B, int N) {
    int r = blockIdx.x * blockDim.x + threadIdx.x;
    const float* src; __half* dst; float* ndst; int row, nrow;
    if (r < NPAD)          { src = sf; dst = g_sfh; ndst = g_snorm;  row = r;            nrow = N; }
    else if (r < 2 * NPAD) { src = f1; dst = g_f1h; ndst = g_f1norm; row = r - NPAD;     nrow = N; }
    else if (r < 3 * NPAD) { src = f2; dst = g_f2h; ndst = g_f2norm; row = r - 2 * NPAD; nrow = N; }
    else                   { src = x;  dst = g_xh;  ndst = g_xnorm;  row = r - 3 * NPAD; nrow = B;
                             if (row >= B) return; }
    bool ok = row < nrow;
    float s = 0.f;
#pragma unroll
    for (int k = 0; k < 16; k++) {
        float4 v = ok ? ((const float4*)(src + (size_t)row * 64))[k] : make_float4(0.f, 0.f, 0.f, 0.f);
        __half h0 = __float2half_rn(v.x), h1 = __float2half_rn(v.y);
        __half h2v = __float2half_rn(v.z), h3 = __float2half_rn(v.w);
        float a = __half2float(h0), b = __half2float(h1);
        float c = __half2float(h2v), d = __half2float(h3);
        __half2 p0; p0.x = h0; p0.y = h1;
        __half2 p1; p1.x = h2v; p1.y = h3;
        ((__half2*)(dst + (size_t)row * 64))[2 * k]     = p0;
        ((__half2*)(dst + (size_t)row * 64))[2 * k + 1] = p1;
        s = fmaf(a, a, fmaf(b, b, fmaf(c, c, fmaf(d, d, s))));
    }
    ndst[row] = ok ? s : 1e4f;
}

// transposed fp16: f1/f2 -> g_Vh [c][i], sl -> g_slTh
__global__ void cvtTh_kernel(const float* __restrict__ f1, const float* __restrict__ f2,
                             const float* __restrict__ sl, int N) {
    __shared__ float tile[32][33];
    int combo = blockIdx.y;
    int i0 = blockIdx.x * 32;
    const float* src; __half* dst; int d0, ncol, outrow0;
    if (combo < 2)      { src = f1; dst = g_Vh;   d0 = combo * 32;       ncol = 64; outrow0 = d0; }
    else if (combo < 4) { src = f2; dst = g_Vh;   d0 = (combo - 2) * 32; ncol = 64; outrow0 = 64 + d0; }
    else                { src = sl; dst = g_slTh; d0 = 0;                ncol = 32; outrow0 = 0; }
    int txx = threadIdx.x, tyy = threadIdx.y;
#pragma unroll
    for (int r = tyy; r < 32; r += 8) {
        int i = i0 + r;
        tile[r][txx] = (i < N) ? src[(size_t)i * ncol + d0 + txx] : 0.f;
    }
    __syncthreads();
#pragma unroll
    for (int rr = tyy; rr < 32; rr += 8)
        dst[(size_t)(outrow0 + rr) * NPAD + i0 + txx] = __float2half_rn(tile[txx][rr]);
}

__global__ void cvtldt_kernel(const float* __restrict__ ld1, const float* __restrict__ ld2,
                              const int* __restrict__ li1, const int* __restrict__ li2,
                              int N, int L) {
    int i = blockIdx.x * 256 + threadIdx.x;
    if (i < L * L) {
        g_ldtb[i] = __float2bfloat16(0.01f * ld1[i]);
        g_ldtb[MAXL * MAXL + i] = __float2bfloat16(0.01f * ld2[i]);
    }
    if (i < NPAD) {
        g_li1p[i] = (i < N) ? li1[i] * L : 0;
        g_li2p[i] = (i < N) ? li2[i] * L : 0;
    }
}

// dummy: shifts pass1 to launch #6 (ncu -s 5 -c 1 target)
__global__ void dummy_kernel() {}

// ---------------- Pass 1 (fp16 HMMA k16, double-buffered, 2 CTAs/SM, E in regs) ----------------
struct __align__(16) SmP1 {
    __half Qs[128][RSH];
    __half Ks[2][64][RSH];
    __half VTs[2][128][RSH];
    float  knp[2][64];
};

__global__ void __launch_bounds__(256, 2) pass1_kernel(int B, int N, int chunk) {
    extern __shared__ char smraw[];
    SmP1& sm = *reinterpret_cast<SmP1*>(smraw);
    int t = threadIdx.x, w = t >> 5, lane = t & 31, g = lane >> 2, tt = lane & 3;
    int qbase = blockIdx.x * 128;
    int i0base = blockIdx.y * chunk;
    int iend = min(i0base + chunk, NPAD);
    int ntl = (iend - i0base) >> 6;
    int qA = w * 16 + g, qB = qA + 8;
    float qnA = g_xnorm[qbase + qA], qnB = g_xnorm[qbase + qB];

    // Q tile: 128 rows x 8 chunks(16B) = 1024
#pragma unroll
    for (int k = 0; k < 4; k++) {
        int gc = t + 256 * k, row = gc >> 3, ch = gc & 7;
        cpa16(saddr(&sm.Qs[row][ch * 8]), g_xh + (size_t)(qbase + row) * 64 + ch * 8);
    }
#define P1_LOAD(i0v, bi)                                                                       \
    {                                                                                          \
        _Pragma("unroll") for (int k = 0; k < 2; k++) {                                        \
            int gc = t + 256 * k, row = gc >> 3, ch = gc & 7;                                  \
            cpa16(saddr(&sm.Ks[bi][row][ch * 8]), g_sfh + (size_t)((i0v) + row) * 64 + ch * 8); } \
        _Pragma("unroll") for (int k = 0; k < 4; k++) {                                        \
            int gc = t + 256 * k, row = gc >> 3, ch = gc & 7;                                  \
            cpa16(saddr(&sm.VTs[bi][row][ch * 8]), g_Vh + (size_t)row * NPAD + (i0v) + ch * 8); } \
        if (t < 16) cpa16(saddr(&sm.knp[bi][t * 4]), g_snorm + (i0v) + t * 4);                 \
        cpa_commit();                                                                          \
    }
    P1_LOAD(i0base, 0);

    float C2[16][4];
#pragma unroll
    for (int a = 0; a < 16; a++) { C2[a][0] = 0.f; C2[a][1] = 0.f; C2[a][2] = 0.f; C2[a][3] = 0.f; }
    float denA = 0.f, denB = 0.f;
    int mmA = 0x7fffffff, mmB = 0x7fffffff;

    for (int it = 0; it < ntl; it++) {
        int bi = it & 1;
        int i0 = i0base + it * 64;
        cpa_wait0();
        __syncthreads();
        if (it + 1 < ntl) P1_LOAD(i0 + 64, bi ^ 1);

        // ---- QK: k16 x 4 groups, 8 n-blocks ----
        float c[8][4];
#pragma unroll
        for (int a = 0; a < 8; a++) { c[a][0] = 0.f; c[a][1] = 0.f; c[a][2] = 0.f; c[a][3] = 0.f; }
#pragma unroll
        for (int kt = 0; kt < 4; kt++) {
            uint32_t a0 = *(const uint32_t*)&sm.Qs[qA][kt * 16 + 2 * tt];
            uint32_t a1 = *(const uint32_t*)&sm.Qs[qB][kt * 16 + 2 * tt];
            uint32_t a2 = *(const uint32_t*)&sm.Qs[qA][kt * 16 + 8 + 2 * tt];
            uint32_t a3 = *(const uint32_t*)&sm.Qs[qB][kt * 16 + 8 + 2 * tt];
#pragma unroll
            for (int nt = 0; nt < 8; nt++) {
                uint32_t b0 = *(const uint32_t*)&sm.Ks[bi][nt * 8 + g][kt * 16 + 2 * tt];
                uint32_t b1 = *(const uint32_t*)&sm.Ks[bi][nt * 8 + g][kt * 16 + 8 + 2 * tt];
                mma_f16(c[nt], a0, a1, a2, a3, b0, b1);
            }
        }

        // ---- scores -> E fragments (registers only) ----
        uint32_t ea0[4], ea1[4], ea2[4], ea3[4];
#pragma unroll
        for (int nt = 0; nt < 8; nt++) {
            int j0 = nt * 8 + 2 * tt;
            float k0 = sm.knp[bi][j0], k1 = sm.knp[bi][j0 + 1];
            float rA0 = qnA + k0 - 2.f * c[nt][0];
            float rA1 = qnA + k1 - 2.f * c[nt][1];
            float rB0 = qnB + k0 - 2.f * c[nt][2];
            float rB1 = qnB + k1 - 2.f * c[nt][3];
            if (rA0 <= 2e-4f) mmA = min(mmA, i0 + j0);
            if (rA1 <= 2e-4f) mmA = min(mmA, i0 + j0 + 1);
            if (rB0 <= 2e-4f) mmB = min(mmB, i0 + j0);
            if (rB1 <= 2e-4f) mmB = min(mmB, i0 + j0 + 1);
            float eA0 = h16r(__expf(-fmaxf(rA0, 0.f)));
            float eA1 = h16r(__expf(-fmaxf(rA1, 0.f)));
            float eB0 = h16r(__expf(-fmaxf(rB0, 0.f)));
            float eB1 = h16r(__expf(-fmaxf(rB1, 0.f)));
            denA += eA0 + eA1; denB += eB0 + eB1;
            if ((nt & 1) == 0) { ea0[nt >> 1] = h2(eA0, eA1); ea1[nt >> 1] = h2(eB0, eB1); }
            else               { ea2[nt >> 1] = h2(eA0, eA1); ea3[nt >> 1] = h2(eB0, eB1); }
        }

        // ---- EV: C2[16q x 128c] += E[16x64] @ V[64x128] ----
#pragma unroll
        for (int ekt = 0; ekt < 4; ekt++) {
#pragma unroll
            for (int nt2 = 0; nt2 < 16; nt2++) {
                uint32_t b0 = *(const uint32_t*)&sm.VTs[bi][nt2 * 8 + g][ekt * 16 + 2 * tt];
                uint32_t b1 = *(const uint32_t*)&sm.VTs[bi][nt2 * 8 + g][ekt * 16 + 8 + 2 * tt];
                mma_f16(C2[nt2], ea0[ekt], ea1[ekt], ea2[ekt], ea3[ekt], b0, b1);
            }
        }
    }

    // ---- epilogue ----
#pragma unroll
    for (int nt2 = 0; nt2 < 16; nt2++) {
        int col = nt2 * 8 + 2 * tt;
        float* base = (col < 64) ? g_acc1 : g_acc2;
        int cc = col & 63;
        atomicAdd(base + (size_t)(qbase + qA) * 64 + cc,     C2[nt2][0]);
        atomicAdd(base + (size_t)(qbase + qA) * 64 + cc + 1, C2[nt2][1]);
        atomicAdd(base + (size_t)(qbase + qB) * 64 + cc,     C2[nt2][2]);
        atomicAdd(base + (size_t)(qbase + qB) * 64 + cc + 1, C2[nt2][3]);
    }
    denA += __shfl_xor_sync(0xffffffffu, denA, 1);
    denA += __shfl_xor_sync(0xffffffffu, denA, 2);
    denB += __shfl_xor_sync(0xffffffffu, denB, 1);
    denB += __shfl_xor_sync(0xffffffffu, denB, 2);
    mmA = min(mmA, __shfl_xor_sync(0xffffffffu, mmA, 1));
    mmA = min(mmA, __shfl_xor_sync(0xffffffffu, mmA, 2));
    mmB = min(mmB, __shfl_xor_sync(0xffffffffu, mmB, 1));
    mmB = min(mmB, __shfl_xor_sync(0xffffffffu, mmB, 2));
    if (tt == 0) {
        atomicAdd(&g_den[qbase + qA], denA);
        atomicAdd(&g_den[qbase + qB], denB);
        if (mmA != 0x7fffffff) atomicMin(&g_match[qbase + qA], mmA);
        if (mmB != 0x7fffffff) atomicMin(&g_match[qbase + qB], mmB);
    }
}

// ---------------- mid ----------------
__global__ void mid_kernel(const float* __restrict__ f1, const float* __restrict__ f2,
                           const float* __restrict__ W1, const float* __restrict__ b1,
                           const float* __restrict__ W2, const float* __restrict__ b2,
                           const float* __restrict__ u1, const float* __restrict__ u2,
                           int B, int N, int DY, int L) {
    __shared__ float sxt[8][2][64];
    __shared__ float sy[8][2][32];
    int wl = threadIdx.x >> 5;
    int lane = threadIdx.x & 31;
    int b = blockIdx.x * 8 + wl;
    if (b >= B) return;

    float inv = 1.0f / g_den[b];
    int d0 = lane, d1 = lane + 32;
    float x10 = g_acc1[(size_t)b * 64 + d0] * inv;
    float x11 = g_acc1[(size_t)b * 64 + d1] * inv;
    float x20 = g_acc2[(size_t)b * 64 + d0] * inv;
    float x21 = g_acc2[(size_t)b * 64 + d1] * inv;
    int m = g_match[b];
    if (m < N) {
        x10 = f1[(size_t)m * 64 + d0]; x11 = f1[(size_t)m * 64 + d1];
        x20 = f2[(size_t)m * 64 + d0]; x21 = f2[(size_t)m * 64 + d1];
    }
    __half hh10 = __float2half_rn(x10), hh11 = __float2half_rn(x11);
    __half hh20 = __float2half_rn(x20), hh21 = __float2half_rn(x21);
    g_xth1[b * 64 + d0] = hh10; g_xth1[b * 64 + d1] = hh11;
    g_xth2[b * 64 + d0] = hh20; g_xth2[b * 64 + d1] = hh21;
    float r10 = __half2float(hh10), r11 = __half2float(hh11);
    float r20 = __half2float(hh20), r21 = __half2float(hh21);
    sxt[wl][0][d0] = x10; sxt[wl][0][d1] = x11;
    sxt[wl][1][d0] = x20; sxt[wl][1][d1] = x21;
    float nr1 = r10 * r10 + r11 * r11;
    float nr2 = r20 * r20 + r21 * r21;
#pragma unroll
    for (int o = 16; o; o >>= 1) {
        nr1 += __shfl_xor_sync(0xffffffffu, nr1, o);
        nr2 += __shfl_xor_sync(0xffffffffu, nr2, o);
    }
    if (lane == 0) { g_xtn1[b] = nr1; g_xtn2[b] = nr2; }
    __syncwarp();

    if (lane < DY) {
        float y1 = b1[lane], y2 = b2[lane];
#pragma unroll
        for (int d = 0; d < 64; d++) {
            y1 = fmaf(sxt[wl][0][d], W1[d * DY + lane], y1);
            y2 = fmaf(sxt[wl][1][d], W2[d * DY + lane], y2);
        }
        sy[wl][0][lane] = y1; sy[wl][1][lane] = y2;
    }
    __syncwarp();

    float best1 = 1e38f, best2 = 1e38f; int bi1 = 0x7fffffff, bi2 = 0x7fffffff;
    for (int lab = lane; lab < L; lab += 32) {
        float s1 = 0.f, s2 = 0.f;
        for (int dy = 0; dy < DY; dy++) {
            float t1 = sy[wl][0][dy] - u1[lab * DY + dy]; s1 = fmaf(t1, t1, s1);
            float t2 = sy[wl][1][dy] - u2[lab * DY + dy]; s2 = fmaf(t2, t2, s2);
        }
        if (s1 < best1) { best1 = s1; bi1 = lab; }
        if (s2 < best2) { best2 = s2; bi2 = lab; }
    }
#pragma unroll
    for (int o = 16; o; o >>= 1) {
        float ob = __shfl_xor_sync(0xffffffffu, best1, o);
        int obi  = __shfl_xor_sync(0xffffffffu, bi1, o);
        if (ob < best1 || (ob == best1 && obi < bi1)) { best1 = ob; bi1 = obi; }
        ob  = __shfl_xor_sync(0xffffffffu, best2, o);
        obi = __shfl_xor_sync(0xffffffffu, bi2, o);
        if (ob < best2 || (ob == best2 && obi < bi2)) { best2 = ob; bi2 = obi; }
    }
    if (lane == 0) { g_yidx1[b] = bi1; g_yidx2[b] = bi2; }
}

// ---------------- Pass 2 (fp16 HMMA k16, double-buffered, 2 CTAs/SM, E in regs) ----------------
struct __align__(16) SmP2 {
    __half Qs[128][RSH];
    __half Ks[2][64][RSH];
    __half VTs[2][32][RSH];
    __nv_bfloat16 ldp[MAXL * MAXL];
    float  knp[2][64];
    int    jli[2][64];
};

__global__ void __launch_bounds__(256, 2) pass2_kernel(int B, int N, int L, int chunk) {
    extern __shared__ char smraw[];
    SmP2& sm = *reinterpret_cast<SmP2*>(smraw);
    int t = threadIdx.x, w = t >> 5, lane = t & 31, g = lane >> 2, tt = lane & 3;
    int z = blockIdx.z;
    const __half* Qg = z ? g_xth2 : g_xth1;
    const __half* Kg = z ? g_f2h : g_f1h;
    const float* kng = z ? g_f2norm : g_f1norm;
    const float* qng = z ? g_xtn2 : g_xtn1;
    const int* lip = z ? g_li2p : g_li1p;
    const int* yix = z ? g_yidx2 : g_yidx1;

    int qbase = blockIdx.x * 128;
    int i0base = blockIdx.y * chunk;
    int iend = min(i0base + chunk, NPAD);
    int ntl = (iend - i0base) >> 6;
    int qA = w * 16 + g, qB = qA + 8;
    float qnA = qng[qbase + qA], qnB = qng[qbase + qB];
    int yvA = yix[qbase + qA], yvB = yix[qbase + qB];

#pragma unroll
    for (int k = 0; k < 4; k++) {
        int gc = t + 256 * k, row = gc >> 3, ch = gc & 7;
        cpa16(saddr(&sm.Qs[row][ch * 8]), Qg + (size_t)(qbase + row) * 64 + ch * 8);
    }
#pragma unroll
    for (int k = 0; k < 5; k++) {
        int gc = t + 256 * k;
        if (gc < 1250)
            cpa16(saddr((char*)sm.ldp + gc * 16),
                  (const char*)(g_ldtb + (size_t)z * MAXL * MAXL) + gc * 16);
    }
#define P2_LOAD(i0v, bi)                                                                       \
    {                                                                                          \
        _Pragma("unroll") for (int k = 0; k < 2; k++) {                                        \
            int gc = t + 256 * k, row = gc >> 3, ch = gc & 7;                                  \
            cpa16(saddr(&sm.Ks[bi][row][ch * 8]), Kg + (size_t)((i0v) + row) * 64 + ch * 8); } \
        {                                                                                      \
            int row = t >> 3, ch = t & 7;                                                      \
            if (row < 32)                                                                      \
                cpa16(saddr(&sm.VTs[bi][row][ch * 8]), g_slTh + (size_t)row * NPAD + (i0v) + ch * 8); } \
        if (t < 16) cpa16(saddr(&sm.knp[bi][t * 4]), kng + (i0v) + t * 4);                     \
        else if (t < 32) cpa16(saddr(&sm.jli[bi][(t - 16) * 4]), lip + (i0v) + (t - 16) * 4);  \
        cpa_commit();                                                                          \
    }
    P2_LOAD(i0base, 0);

    float C2[4][4];
#pragma unroll
    for (int a = 0; a < 4; a++) { C2[a][0] = 0.f; C2[a][1] = 0.f; C2[a][2] = 0.f; C2[a][3] = 0.f; }
    float denA = 0.f, denB = 0.f;

    for (int it = 0; it < ntl; it++) {
        int bi = it & 1;
        cpa_wait0();
        __syncthreads();
        if (it + 1 < ntl) P2_LOAD(i0base + (it + 1) * 64, bi ^ 1);

        // ---- QK ----
        float c[8][4];
#pragma unroll
        for (int a = 0; a < 8; a++) { c[a][0] = 0.f; c[a][1] = 0.f; c[a][2] = 0.f; c[a][3] = 0.f; }
#pragma unroll
        for (int kt = 0; kt < 4; kt++) {
            uint32_t a0 = *(const uint32_t*)&sm.Qs[qA][kt * 16 + 2 * tt];
            uint32_t a1 = *(const uint32_t*)&sm.Qs[qB][kt * 16 + 2 * tt];
            uint32_t a2 = *(const uint32_t*)&sm.Qs[qA][kt * 16 + 8 + 2 * tt];
            uint32_t a3 = *(const uint32_t*)&sm.Qs[qB][kt * 16 + 8 + 2 * tt];
#pragma unroll
            for (int nt = 0; nt < 8; nt++) {
                uint32_t b0 = *(const uint32_t*)&sm.Ks[bi][nt * 8 + g][kt * 16 + 2 * tt];
                uint32_t b1 = *(const uint32_t*)&sm.Ks[bi][nt * 8 + g][kt * 16 + 8 + 2 * tt];
                mma_f16(c[nt], a0, a1, a2, a3, b0, b1);
            }
        }

        // ---- scores + bias -> E fragments ----
        uint32_t ea0[4], ea1[4], ea2[4], ea3[4];
#pragma unroll
        for (int nt = 0; nt < 8; nt++) {
            int j0 = nt * 8 + 2 * tt;
            float k0 = sm.knp[bi][j0], k1 = sm.knp[bi][j0 + 1];
            int l0 = sm.jli[bi][j0], l1 = sm.jli[bi][j0 + 1];
            float rA0 = fmaxf(qnA + k0 - 2.f * c[nt][0], 0.f) + __bfloat162float(sm.ldp[l0 + yvA]);
            float rA1 = fmaxf(qnA + k1 - 2.f * c[nt][1], 0.f) + __bfloat162float(sm.ldp[l1 + yvA]);
            float rB0 = fmaxf(qnB + k0 - 2.f * c[nt][2], 0.f) + __bfloat162float(sm.ldp[l0 + yvB]);
            float rB1 = fmaxf(qnB + k1 - 2.f * c[nt][3], 0.f) + __bfloat162float(sm.ldp[l1 + yvB]);
            float eA0 = h16r(__expf(-rA0));
            float eA1 = h16r(__expf(-rA1));
            float eB0 = h16r(__expf(-rB0));
            float eB1 = h16r(__expf(-rB1));
            denA += eA0 + eA1; denB += eB0 + eB1;
            if ((nt & 1) == 0) { ea0[nt >> 1] = h2(eA0, eA1); ea1[nt >> 1] = h2(eB0, eB1); }
            else               { ea2[nt >> 1] = h2(eA0, eA1); ea3[nt >> 1] = h2(eB0, eB1); }
        }

        // ---- EV: C2[16q x 32c] ----
#pragma unroll
        for (int ekt = 0; ekt < 4; ekt++) {
#pragma unroll
            for (int nt2 = 0; nt2 < 4; nt2++) {
                uint32_t b0 = *(const uint32_t*)&sm.VTs[bi][nt2 * 8 + g][ekt * 16 + 2 * tt];
                uint32_t b1 = *(const uint32_t*)&sm.VTs[bi][nt2 * 8 + g][ekt * 16 + 8 + 2 * tt];
                mma_f16(C2[nt2], ea0[ekt], ea1[ekt], ea2[ekt], ea3[ekt], b0, b1);
            }
        }
    }

    // ---- epilogue ----
    float* outb = g_out2 + (size_t)z * B * 32;
#pragma unroll
    for (int nt2 = 0; nt2 < 4; nt2++) {
        int col = nt2 * 8 + 2 * tt;
        atomicAdd(outb + (size_t)(qbase + qA) * 32 + col,     C2[nt2][0]);
        atomicAdd(outb + (size_t)(qbase + qA) * 32 + col + 1, C2[nt2][1]);
        atomicAdd(outb + (size_t)(qbase + qB) * 32 + col,     C2[nt2][2]);
        atomicAdd(outb + (size_t)(qbase + qB) * 32 + col + 1, C2[nt2][3]);
    }
    denA += __shfl_xor_sync(0xffffffffu, denA, 1);
    denA += __shfl_xor_sync(0xffffffffu, denA, 2);
    denB += __shfl_xor_sync(0xffffffffu, denB, 1);
    denB += __shfl_xor_sync(0xffffffffu, denB, 2);
    if (tt == 0) {
        atomicAdd(&g_den2[(size_t)z * B + qbase + qA], denA);
        atomicAdd(&g_den2[(size_t)z * B + qbase + qB], denB);
    }
}

// ---------------- final ----------------
__global__ void final_kernel(float* __restrict__ out, int B, int DY) {
    int idx = blockIdx.x * blockDim.x + threadIdx.x;
    if (idx >= B * DY) return;
    int b = idx >> 5;
    out[idx] = 0.5f * (g_out2[idx] / g_den2[b] + g_out2[(size_t)B * 32 + idx] / g_den2[B + b]);
}

// ---------------- launch ----------------
extern "C" void kernel_launch(void* const* d_in, const int* in_sizes, int n_in,
                              void* d_out, int out_size) {
    const float* x   = (const float*)d_in[0];
    const float* sf  = (const float*)d_in[1];
    const float* sl  = (const float*)d_in[2];
    const float* f1  = (const float*)d_in[3];
    const float* f2  = (const float*)d_in[4];
    const float* u1  = (const float*)d_in[5];
    const float* u2  = (const float*)d_in[6];
    const float* ld1 = (const float*)d_in[7];
    const float* ld2 = (const float*)d_in[8];
    const float* W1  = (const float*)d_in[9];
    const float* b1  = (const float*)d_in[10];
    const float* W2  = (const float*)d_in[11];
    const float* b2  = (const float*)d_in[12];
    const int*   li1 = (const int*)d_in[13];
    const int*   li2 = (const int*)d_in[14];

    int DY = in_sizes[10];            // 32
    int Dd = in_sizes[9] / DY;        // 64
    int B  = in_sizes[0] / Dd;        // 2048
    int N  = in_sizes[1] / Dd;        // 20000
    int L  = in_sizes[5] / DY;        // 100

    int ntiles = NPAD / 64;                           // 313
    int chunk1 = ((ntiles + NS1 - 1) / NS1) * 64;     // 1152
    int chunk2 = ((ntiles + NS2 - 1) / NS2) * 64;     // 2240

    cudaFuncSetAttribute(pass1_kernel, cudaFuncAttributeMaxDynamicSharedMemorySize, (int)sizeof(SmP1));
    cudaFuncSetAttribute(pass2_kernel, cudaFuncAttributeMaxDynamicSharedMemorySize, (int)sizeof(SmP2));

    init_kernel<<<(B * 64 + 255) / 256, 256>>>(B);
    cvth_kernel<<<(3 * NPAD + MAXB + 255) / 256, 256>>>(x, sf, f1, f2, B, N);
    cvtTh_kernel<<<dim3(NPAD / 32, 5), dim3(32, 8)>>>(f1, f2, sl, N);
    cvtldt_kernel<<<(NPAD + 255) / 256, 256>>>(ld1, ld2, li1, li2, N, L);
    dummy_kernel<<<1, 32>>>();   // shift pass1 to launch #6 (ncu -s 5 -c 1 target)

    pass1_kernel<<<dim3(B / 128, NS1), 256, sizeof(SmP1)>>>(B, N, chunk1);

    mid_kernel<<<B / 8, 256>>>(f1, f2, W1, b1, W2, b2, u1, u2, B, N, DY, L);

    pass2_kernel<<<dim3(B / 128, NS2, 2), 256, sizeof(SmP2)>>>(B, N, L, chunk2);

    final_kernel<<<(B * DY + 255) / 256, 256>>>((float*)d_out, B, DY);
}